// round 16
// baseline (speedup 1.0000x reference)
#include <cuda_runtime.h>
#include <cstdint>

// ifft(fft(x)) == x (identity). Output confirmed (R3): n float32, real part.
// Pure HBM-bound 256MB -> 256MB streaming copy.
//
// FINAL — converged; 7 consecutive runs in the 75.6-76.7us / 6.30-6.40 TB/s
// band (documented LTS run-to-run variation). Search-space characterization:
//   copy4, 16384 blocks (THIS):   75.6-76.7us, 6304-6398 GB/s <- best (x7)
//   copy8,  8192 blocks:          76.4us, 6313 GB/s  (LTS-cap neutral)
//   persistent grid-stride 2048:  80.5us, 6038 GB/s  (loop-carried dep
//                                                     kills per-SM MLP)
//   copy-engine memcpy node:      ~80us              (slower path)
// ~6.37 TB/s is this chip's path-independent streaming ceiling; this kernel
// sits on it. The ~8us dur_us-kernel residual is fixed harness graph-replay
// overhead, invariant across all variants tested.

__global__ __launch_bounds__(256) void copy4_kernel(
    const float4* __restrict__ in, float4* __restrict__ out, long long n_vec4)
{
    // Block b owns float4 range [b*1024, b*1024+1024): 4 coalesced 4KB chunks.
    long long base = (long long)blockIdx.x * 1024 + threadIdx.x;
    long long i0 = base, i1 = base + 256, i2 = base + 512, i3 = base + 768;

    if (i3 < n_vec4) {
        // Fast path: front-batched loads (MLP=4), streaming hints (touch-once).
        float4 a0 = __ldcs(in + i0);
        float4 a1 = __ldcs(in + i1);
        float4 a2 = __ldcs(in + i2);
        float4 a3 = __ldcs(in + i3);
        __stcs(out + i0, a0);
        __stcs(out + i1, a1);
        __stcs(out + i2, a2);
        __stcs(out + i3, a3);
    } else {
        if (i0 < n_vec4) __stcs(out + i0, __ldcs(in + i0));
        if (i1 < n_vec4) __stcs(out + i1, __ldcs(in + i1));
        if (i2 < n_vec4) __stcs(out + i2, __ldcs(in + i2));
    }
}

// ---- Case B guard: expand n floats -> 2n floats (re, 0, ...) -----------
__global__ __launch_bounds__(256) void expand_kernel(
    const float4* __restrict__ in, float4* __restrict__ out, long long n_vec4)
{
    long long i = (long long)blockIdx.x * blockDim.x + threadIdx.x;
    if (i >= n_vec4) return;
    float4 a = __ldcs(in + i);
    long long o = i * 2;
    __stcs(out + o,     make_float4(a.x, 0.0f, a.y, 0.0f));
    __stcs(out + o + 1, make_float4(a.z, 0.0f, a.w, 0.0f));
}

// ---- Fallback: scalar, handles any size/alignment ----------------------
__global__ void scalar_kernel(const float* __restrict__ in,
                              float* __restrict__ out,
                              long long n_in, long long n_out)
{
    long long i = (long long)blockIdx.x * blockDim.x + threadIdx.x;
    long long stride = (long long)gridDim.x * blockDim.x;
    if (n_out == n_in) {
        for (long long j = i; j < n_out; j += stride) out[j] = in[j];
    } else {
        for (long long j = i; j < n_out; j += stride)
            out[j] = (j & 1) ? 0.0f : in[j >> 1];
    }
}

extern "C" void kernel_launch(void* const* d_in, const int* in_sizes, int n_in,
                              void* d_out, int out_size) {
    const float* x = (const float*)d_in[0];
    long long n = (long long)in_sizes[0];
    long long nout = (long long)out_size;

    bool aligned = ((uintptr_t)x % 16 == 0) && ((uintptr_t)d_out % 16 == 0);

    if (nout == n && aligned && (n % 4 == 0)) {
        long long n_vec4 = n / 4;                 // 2^24 for this shape
        long long grid = (n_vec4 + 1023) / 1024;  // 16384 blocks of 256
        copy4_kernel<<<(unsigned)grid, 256>>>(
            (const float4*)x, (float4*)d_out, n_vec4);
    } else if (nout == 2 * n && aligned && (n % 4 == 0)) {
        long long n_vec4 = n / 4;
        long long grid = (n_vec4 + 255) / 256;
        expand_kernel<<<(unsigned)grid, 256>>>(
            (const float4*)x, (float4*)d_out, n_vec4);
    } else {
        long long grid = (nout + 255) / 256;
        if (grid > 2147483647LL) grid = 2147483647LL;
        scalar_kernel<<<(unsigned)grid, 256>>>(x, (float*)d_out, n, nout);
    }
}

// round 17
// speedup vs baseline: 1.0004x; 1.0004x over previous
#include <cuda_runtime.h>
#include <cstdint>

// ifft(fft(x)) == x (identity). Output confirmed (R3): n float32, real part.
// Pure HBM-bound 256MB -> 256MB streaming copy.
//
// FINAL — converged; 8 consecutive runs in the 75.6-76.7us / 6.30-6.40 TB/s
// band (documented LTS run-to-run variation). Search-space characterization:
//   copy4, 16384 blocks (THIS):   75.6-76.7us, 6304-6398 GB/s <- best (x8)
//   copy8,  8192 blocks:          76.4us, 6313 GB/s  (LTS-cap neutral)
//   persistent grid-stride 2048:  80.5us, 6038 GB/s  (loop-carried dep
//                                                     kills per-SM MLP)
//   copy-engine memcpy node:      ~80us              (slower path)
// ~6.37 TB/s is this chip's path-independent streaming ceiling; this kernel
// sits on it. The ~8us dur_us-kernel residual is fixed harness graph-replay
// overhead, invariant across all variants tested.

__global__ __launch_bounds__(256) void copy4_kernel(
    const float4* __restrict__ in, float4* __restrict__ out, long long n_vec4)
{
    // Block b owns float4 range [b*1024, b*1024+1024): 4 coalesced 4KB chunks.
    long long base = (long long)blockIdx.x * 1024 + threadIdx.x;
    long long i0 = base, i1 = base + 256, i2 = base + 512, i3 = base + 768;

    if (i3 < n_vec4) {
        // Fast path: front-batched loads (MLP=4), streaming hints (touch-once).
        float4 a0 = __ldcs(in + i0);
        float4 a1 = __ldcs(in + i1);
        float4 a2 = __ldcs(in + i2);
        float4 a3 = __ldcs(in + i3);
        __stcs(out + i0, a0);
        __stcs(out + i1, a1);
        __stcs(out + i2, a2);
        __stcs(out + i3, a3);
    } else {
        if (i0 < n_vec4) __stcs(out + i0, __ldcs(in + i0));
        if (i1 < n_vec4) __stcs(out + i1, __ldcs(in + i1));
        if (i2 < n_vec4) __stcs(out + i2, __ldcs(in + i2));
    }
}

// ---- Case B guard: expand n floats -> 2n floats (re, 0, ...) -----------
__global__ __launch_bounds__(256) void expand_kernel(
    const float4* __restrict__ in, float4* __restrict__ out, long long n_vec4)
{
    long long i = (long long)blockIdx.x * blockDim.x + threadIdx.x;
    if (i >= n_vec4) return;
    float4 a = __ldcs(in + i);
    long long o = i * 2;
    __stcs(out + o,     make_float4(a.x, 0.0f, a.y, 0.0f));
    __stcs(out + o + 1, make_float4(a.z, 0.0f, a.w, 0.0f));
}

// ---- Fallback: scalar, handles any size/alignment ----------------------
__global__ void scalar_kernel(const float* __restrict__ in,
                              float* __restrict__ out,
                              long long n_in, long long n_out)
{
    long long i = (long long)blockIdx.x * blockDim.x + threadIdx.x;
    long long stride = (long long)gridDim.x * blockDim.x;
    if (n_out == n_in) {
        for (long long j = i; j < n_out; j += stride) out[j] = in[j];
    } else {
        for (long long j = i; j < n_out; j += stride)
            out[j] = (j & 1) ? 0.0f : in[j >> 1];
    }
}

extern "C" void kernel_launch(void* const* d_in, const int* in_sizes, int n_in,
                              void* d_out, int out_size) {
    const float* x = (const float*)d_in[0];
    long long n = (long long)in_sizes[0];
    long long nout = (long long)out_size;

    bool aligned = ((uintptr_t)x % 16 == 0) && ((uintptr_t)d_out % 16 == 0);

    if (nout == n && aligned && (n % 4 == 0)) {
        long long n_vec4 = n / 4;                 // 2^24 for this shape
        long long grid = (n_vec4 + 1023) / 1024;  // 16384 blocks of 256
        copy4_kernel<<<(unsigned)grid, 256>>>(
            (const float4*)x, (float4*)d_out, n_vec4);
    } else if (nout == 2 * n && aligned && (n % 4 == 0)) {
        long long n_vec4 = n / 4;
        long long grid = (n_vec4 + 255) / 256;
        expand_kernel<<<(unsigned)grid, 256>>>(
            (const float4*)x, (float4*)d_out, n_vec4);
    } else {
        long long grid = (nout + 255) / 256;
        if (grid > 2147483647LL) grid = 2147483647LL;
        scalar_kernel<<<(unsigned)grid, 256>>>(x, (float*)d_out, n, nout);
    }
}